// round 2
// baseline (speedup 1.0000x reference)
#include <cuda_runtime.h>
#include <math.h>

#define L 2048
#define DE 768
#define DV 64
#define NH 12
#define DMLP 3072
#define VOCAB 32000
#define NLAYERS 4
#define NSEL 75     // 11 head-col0 + 64 cols of head 11
#define YCOLS 80    // padded

// ------------------------- device scratch (no cudaMalloc allowed) ----------
__device__ float g_Y[L * DE];
__device__ float g_xn[L * DE];
__device__ float g_zn[L * DE];
__device__ float g_R[L * DE];
__device__ float g_Qb[NH * L * DE];
__device__ float g_Kb[NH * L * DE];
__device__ float g_KTb[NH * DE * L];
__device__ float g_S[NH * L * L];
__device__ float g_vsel[L * YCOLS];
__device__ float g_Wsel[DE * YCOLS];
__device__ float g_bsel[YCOLS];
__device__ float g_yattn[L * YCOLS];
__device__ float g_mlp[L * DMLP];
__device__ float g_logits[L * VOCAB];

// ------------------------- helpers ----------------------------------------
__device__ __forceinline__ float gelu_tanh(float x) {
    const float c = 0.7978845608028654f;   // sqrt(2/pi)
    float x3 = x * x * x;
    return 0.5f * x * (1.0f + tanhf(c * (x + 0.044715f * x3)));
}

// ------------------------- GEMM -------------------------------------------
// C[M,N] = mode0: alpha*A@B + bias
//          mode1: gelu(alpha*A@B + bias)
//          mode2: alpha*A@B + bias + resScale*D     (D has ld = ldc)
// batched over blockIdx.z with element strides sA/sB/sC/sBias.
#define GBM 128
#define GBN 128
#define GBK 8

__global__ __launch_bounds__(256)
void sgemm_kernel(const float* __restrict__ A, long long sA,
                  const float* __restrict__ B, long long sB,
                  float* __restrict__ C, long long sC,
                  const float* __restrict__ bias, long long sBias,
                  const float* __restrict__ D,
                  int M, int N, int K, int lda, int ldb, int ldc,
                  float alpha, float resScale, int mode)
{
    long long z = blockIdx.z;
    A += z * sA;
    B += z * sB;
    C += z * sC;
    if (bias) bias += z * sBias;

    __shared__ float As[GBK][GBM + 4];   // A transposed: As[k][m]
    __shared__ float Bs[GBK][GBN];

    const int tid = threadIdx.x;           // 256 threads
    const int tr  = tid >> 4;              // 0..15
    const int tc  = tid & 15;              // 0..15
    const int row0 = blockIdx.y * GBM;
    const int col0 = blockIdx.x * GBN;

    float acc[8][8];
#pragma unroll
    for (int i = 0; i < 8; i++)
#pragma unroll
        for (int j = 0; j < 8; j++) acc[i][j] = 0.0f;

    const int a_r  = tid >> 1;             // 0..127
    const int a_kq = (tid & 1) * 4;        // 0 or 4
    const int b_kk = tid >> 5;             // 0..7
    const int b_n  = tid & 31;             // 0..31

    for (int k0 = 0; k0 < K; k0 += GBK) {
        // A tile: 128 rows x 8 k (transposed into As)
        {
            int grow = row0 + a_r;
            bool rok = (grow < M);
            const float* Ap = A + (long long)grow * lda + k0 + a_kq;
#pragma unroll
            for (int j = 0; j < 4; j++) {
                int gk = k0 + a_kq + j;
                float v = (rok && gk < K) ? Ap[j] : 0.0f;
                As[a_kq + j][a_r] = v;
            }
        }
        // B tile: 8 k x 128 n (coalesced: 32 consecutive n per j-step)
        {
            int gk = k0 + b_kk;
            bool kok = (gk < K);
            const float* Bp = B + (long long)gk * ldb + col0 + b_n;
#pragma unroll
            for (int j = 0; j < 4; j++) {
                int gn = col0 + b_n + 32 * j;
                float v = (kok && gn < N) ? Bp[32 * j] : 0.0f;
                Bs[b_kk][b_n + 32 * j] = v;
            }
        }
        __syncthreads();

#pragma unroll
        for (int kk = 0; kk < GBK; kk++) {
            float a[8], b[8];
#pragma unroll
            for (int i = 0; i < 8; i++) a[i] = As[kk][tr * 8 + i];
#pragma unroll
            for (int j = 0; j < 8; j++) b[j] = Bs[kk][tc * 8 + j];
#pragma unroll
            for (int i = 0; i < 8; i++)
#pragma unroll
                for (int j = 0; j < 8; j++)
                    acc[i][j] = fmaf(a[i], b[j], acc[i][j]);
        }
        __syncthreads();
    }

#pragma unroll
    for (int i = 0; i < 8; i++) {
        int grow = row0 + tr * 8 + i;
        if (grow >= M) continue;
#pragma unroll
        for (int j = 0; j < 8; j++) {
            int gcol = col0 + tc * 8 + j;
            if (gcol >= N) continue;
            float v = alpha * acc[i][j];
            if (bias) v += bias[gcol];
            if (mode == 1) v = gelu_tanh(v);
            if (mode == 2) v += resScale * D[(long long)grow * ldc + gcol];
            C[(long long)grow * ldc + gcol] = v;
        }
    }
}

// ------------------------- transpose (batched) -----------------------------
__global__ void transpose_kernel(const float* __restrict__ in, float* __restrict__ out,
                                 int rows, int cols)
{
    __shared__ float tile[32][33];
    long long zoff = (long long)blockIdx.z * rows * cols;
    int r0 = blockIdx.y * 32, c0 = blockIdx.x * 32;
    int tx = threadIdx.x, ty = threadIdx.y;     // 32 x 8
#pragma unroll
    for (int i = 0; i < 32; i += 8) {
        int r = r0 + ty + i, c = c0 + tx;
        if (r < rows && c < cols)
            tile[ty + i][tx] = in[zoff + (long long)r * cols + c];
    }
    __syncthreads();
#pragma unroll
    for (int i = 0; i < 32; i += 8) {
        int oc = c0 + ty + i, orr = r0 + tx;    // out index: [col][row]
        if (oc < cols && orr < rows)
            out[zoff + (long long)oc * rows + orr] = tile[tx][ty + i];
    }
}

// ------------------------- layernorm (one block per row) --------------------
__global__ void layernorm_kernel(const float* __restrict__ in, float* __restrict__ out,
                                 const float* __restrict__ gamma, const float* __restrict__ beta)
{
    int row = blockIdx.x;
    const float* x = in + (long long)row * DE;
    float s = 0.f, s2 = 0.f;
    for (int i = threadIdx.x; i < DE; i += 256) { float v = x[i]; s += v; s2 += v * v; }
    __shared__ float sh1[256], sh2[256];
    sh1[threadIdx.x] = s; sh2[threadIdx.x] = s2;
    __syncthreads();
    for (int off = 128; off > 0; off >>= 1) {
        if (threadIdx.x < off) {
            sh1[threadIdx.x] += sh1[threadIdx.x + off];
            sh2[threadIdx.x] += sh2[threadIdx.x + off];
        }
        __syncthreads();
    }
    float mean = sh1[0] / DE;
    float var  = fmaxf(sh2[0] / DE - mean * mean, 0.0f);
    float sd   = sqrtf(var);
    float inv  = (sd == 0.0f) ? 1.0f : 1.0f / sd;
    float* o = out + (long long)row * DE;
    for (int i = threadIdx.x; i < DE; i += 256)
        o[i] = gamma[i] * ((x[i] - mean) * inv) + beta[i];
}

// ------------------------- row softmax (in may equal out) -------------------
__global__ void softmax_kernel(const float* __restrict__ in, float* __restrict__ out, int N)
{
    long long row = blockIdx.x;
    const float* x = in + row * (long long)N;
    float* o = out + row * (long long)N;
    __shared__ float sh[256];
    float m = -3.4e38f;
    for (int i = threadIdx.x; i < N; i += 256) m = fmaxf(m, x[i]);
    sh[threadIdx.x] = m;
    __syncthreads();
    for (int off = 128; off > 0; off >>= 1) {
        if (threadIdx.x < off) sh[threadIdx.x] = fmaxf(sh[threadIdx.x], sh[threadIdx.x + off]);
        __syncthreads();
    }
    m = sh[0];
    __syncthreads();
    float s = 0.f;
    for (int i = threadIdx.x; i < N; i += 256) {
        float e = expf(x[i] - m);
        o[i] = e;
        s += e;
    }
    sh[threadIdx.x] = s;
    __syncthreads();
    for (int off = 128; off > 0; off >>= 1) {
        if (threadIdx.x < off) sh[threadIdx.x] += sh[threadIdx.x + off];
        __syncthreads();
    }
    float invs = 1.0f / sh[0];
    for (int i = threadIdx.x; i < N; i += 256) o[i] *= invs;
}

// ------------------------- attn gemv: y[:,h] = P_h @ vsel[:,h], h<11 --------
__global__ void attn_gemv_kernel(const float* __restrict__ S, const float* __restrict__ vsel,
                                 float* __restrict__ y)
{
    int h = blockIdx.z;        // 0..10
    int row = blockIdx.x;      // 0..L-1
    const float* p = S + ((long long)h * L + row) * L;
    float s = 0.f;
    for (int mi = threadIdx.x; mi < L; mi += 256)
        s += p[mi] * vsel[(long long)mi * YCOLS + h];
    __shared__ float sh[256];
    sh[threadIdx.x] = s;
    __syncthreads();
    for (int off = 128; off > 0; off >>= 1) {
        if (threadIdx.x < off) sh[threadIdx.x] += sh[threadIdx.x + off];
        __syncthreads();
    }
    if (threadIdx.x == 0) y[(long long)row * YCOLS + h] = sh[0];
}

// ------------------------- misc -------------------------------------------
__global__ void embed_kernel(const int* __restrict__ x, const float* __restrict__ we,
                             const float* __restrict__ pe, float* __restrict__ Y)
{
    int i = blockIdx.x * blockDim.x + threadIdx.x;
    if (i >= L * DE) return;
    int l = i / DE, d = i % DE;
    Y[i] = we[(long long)x[l] * DE + d] + pe[i];
}

__global__ void pack_wv_kernel(const float* __restrict__ Wv, const float* __restrict__ bv,
                               float* __restrict__ Wsel, float* __restrict__ bsel, int layer)
{
    int i = blockIdx.x * blockDim.x + threadIdx.x;
    if (i < DE * NSEL) {
        int d = i / NSEL, c = i % NSEL;
        int h  = (c < NH - 1) ? c : (NH - 1);
        int vc = (c < NH - 1) ? 0 : (c - (NH - 1));
        Wsel[(long long)d * YCOLS + c] =
            Wv[(((long long)layer * NH + h) * DE + d) * DV + vc];
    }
    if (i < NSEL) {
        int h  = (i < NH - 1) ? i : (NH - 1);
        int vc = (i < NH - 1) ? 0 : (i - (NH - 1));
        bsel[i] = bv[((long long)layer * NH + h) * DV + vc];
    }
}

__global__ void add_kernel(const float* __restrict__ a, const float* __restrict__ b,
                           float* __restrict__ c)
{
    int i = blockIdx.x * blockDim.x + threadIdx.x;
    if (i < L * DE) c[i] = a[i] + b[i];
}

// ------------------------- host side ---------------------------------------
static void gemm(const float* A, long long sA, const float* B, long long sB,
                 float* C, long long sC, const float* bias, long long sBias,
                 const float* D, int M, int N, int K, int lda, int ldb, int ldc,
                 float alpha, float resScale, int mode, int batch)
{
    dim3 grid((N + GBN - 1) / GBN, (M + GBM - 1) / GBM, batch);
    sgemm_kernel<<<grid, 256>>>(A, sA, B, sB, C, sC, bias, sBias, D,
                                M, N, K, lda, ldb, ldc, alpha, resScale, mode);
}

template <typename T>
static float* sym_addr(T& sym)
{
    void* p = nullptr;
    cudaGetSymbolAddress(&p, sym);
    return (float*)p;
}

extern "C" void kernel_launch(void* const* d_in, const int* in_sizes, int n_in,
                              void* d_out, int out_size)
{
    const int*   x   = (const int*)  d_in[0];
    const float* we  = (const float*)d_in[1];
    const float* pe  = (const float*)d_in[2];
    const float* Wq  = (const float*)d_in[3];
    const float* bq  = (const float*)d_in[4];
    const float* Wk  = (const float*)d_in[5];
    const float* bk  = (const float*)d_in[6];
    const float* Wv  = (const float*)d_in[7];
    const float* bv  = (const float*)d_in[8];
    const float* Wo  = (const float*)d_in[9];
    const float* bo  = (const float*)d_in[10];
    const float* g1  = (const float*)d_in[11];
    const float* be1 = (const float*)d_in[12];
    const float* g2  = (const float*)d_in[13];
    const float* be2 = (const float*)d_in[14];
    const float* W1  = (const float*)d_in[15];
    const float* bm1 = (const float*)d_in[16];
    const float* W2  = (const float*)d_in[17];
    const float* bm2 = (const float*)d_in[18];
    const float* gf  = (const float*)d_in[19];
    const float* bef = (const float*)d_in[20];
    const float* Wu  = (const float*)d_in[21];
    const float* bu  = (const float*)d_in[22];
    float* out = (float*)d_out;

    float* Y    = sym_addr(g_Y);
    float* xn   = sym_addr(g_xn);
    float* zn   = sym_addr(g_zn);
    float* R    = sym_addr(g_R);
    float* Qb   = sym_addr(g_Qb);
    float* Kb   = sym_addr(g_Kb);
    float* KTb  = sym_addr(g_KTb);
    float* S    = sym_addr(g_S);
    float* vsel = sym_addr(g_vsel);
    float* Wsel = sym_addr(g_Wsel);
    float* bsel = sym_addr(g_bsel);
    float* ya   = sym_addr(g_yattn);
    float* mlp  = sym_addr(g_mlp);
    float* lg   = sym_addr(g_logits);

    const float inv_sqrt_de = 0.03608439182435161f;  // 1/sqrt(768)

    embed_kernel<<<(L * DE + 255) / 256, 256>>>(x, we, pe, Y);

    for (int l = 0; l < NLAYERS; l++) {
        // xn = LN(Y; g1, be1)
        layernorm_kernel<<<L, 256>>>(Y, xn, g1 + l * DE, be1 + l * DE);

        // Q, K projections, batched over heads
        gemm(xn, 0, Wq + (long long)l * NH * DE * DE, (long long)DE * DE,
             Qb, (long long)L * DE, bq + (long long)l * NH * DE, DE, nullptr,
             L, DE, DE, DE, DE, DE, 1.0f, 0.0f, 0, NH);
        gemm(xn, 0, Wk + (long long)l * NH * DE * DE, (long long)DE * DE,
             Kb, (long long)L * DE, bk + (long long)l * NH * DE, DE, nullptr,
             L, DE, DE, DE, DE, DE, 1.0f, 0.0f, 0, NH);

        // packed V projection: only columns that survive the overlapping writes
        pack_wv_kernel<<<(DE * NSEL + 255) / 256, 256>>>(Wv, bv, Wsel, bsel, l);
        gemm(xn, 0, Wsel, 0, vsel, 0, bsel, 0, nullptr,
             L, NSEL, DE, DE, YCOLS, YCOLS, 1.0f, 0.0f, 0, 1);

        // K^T per head
        transpose_kernel<<<dim3(DE / 32, L / 32, NH), dim3(32, 8)>>>(Kb, KTb, L, DE);

        // scores = Q @ K^T / sqrt(DE), batched
        gemm(Qb, (long long)L * DE, KTb, (long long)DE * L,
             S, (long long)L * L, nullptr, 0, nullptr,
             L, L, DE, DE, L, L, inv_sqrt_de, 0.0f, 0, NH);

        // row softmax over all heads
        softmax_kernel<<<NH * L, 256>>>(S, S, L);

        // attn: heads 0..10 need only column 0 of V -> gemv into y[:,h]
        attn_gemv_kernel<<<dim3(L, 1, NH - 1), 256>>>(S, vsel, ya);
        // head 11: full 64-wide GEMM into y[:,11:75]
        gemm(S + (long long)(NH - 1) * L * L, 0, vsel + (NH - 1), 0,
             ya + (NH - 1), 0, nullptr, 0, nullptr,
             L, DV, L, L, YCOLS, YCOLS, 1.0f, 0.0f, 0, 1);

        // Y = 2*Y + (y @ Wo + bo), K = 75 (rest of y is zero)
        gemm(ya, 0, Wo + (long long)l * DE * DE, 0, Y, 0,
             bo + l * DE, 0, Y,
             L, DE, NSEL, YCOLS, DE, DE, 1.0f, 2.0f, 2, 1);

        // zn = LN(Y; g2, be2)
        layernorm_kernel<<<L, 256>>>(Y, zn, g2 + l * DE, be2 + l * DE);

        // mlp = gelu(zn @ W1 + bm1)
        gemm(zn, 0, W1 + (long long)l * DE * DMLP, 0, mlp, 0,
             bm1 + (long long)l * DMLP, 0, nullptr,
             L, DMLP, DE, DE, DMLP, DMLP, 1.0f, 0.0f, 1, 1);

        // R = Y + zn ;  Y = R + (mlp @ W2 + bm2)
        add_kernel<<<(L * DE + 255) / 256, 256>>>(Y, zn, R);
        gemm(mlp, 0, W2 + (long long)l * DMLP * DE, 0, Y, 0,
             bm2 + l * DE, 0, R,
             L, DE, DMLP, DMLP, DE, DE, 1.0f, 1.0f, 2, 1);
    }

    // final LN + vocab projection + softmax -> out
    layernorm_kernel<<<L, 256>>>(Y, xn, gf, bef);
    gemm(xn, 0, Wu, 0, lg, 0, bu, 0, nullptr,
         L, VOCAB, DE, DE, VOCAB, VOCAB, 1.0f, 0.0f, 0, 1);
    softmax_kernel<<<L, 256>>>(lg, out, VOCAB);
}

// round 3
// speedup vs baseline: 2.3933x; 2.3933x over previous
#include <cuda_runtime.h>
#include <math.h>
#include <stdint.h>

#define L 2048
#define DE 768
#define DV 64
#define NH 12
#define DMLP 3072
#define VOCAB 32000
#define NLAYERS 4
#define NSEL 75     // 11 head-col0 + 64 cols of head 11
#define YCOLS 80    // padded

// ------------------------- device scratch (no cudaMalloc allowed) ----------
__device__ float g_Y[L * DE];
__device__ float g_xn[L * DE];
__device__ float g_zn[L * DE];
__device__ float g_R[L * DE];
__device__ float g_Qb[NH * L * DE];
__device__ float g_Kb[NH * L * DE];
__device__ float g_S[NH * L * L];
__device__ float g_vsel[L * YCOLS];
__device__ float g_Wsel[DE * YCOLS];
__device__ float g_bsel[YCOLS];
__device__ float g_yattn[L * YCOLS];
__device__ float g_mlp[L * DMLP];
__device__ float g_logits[L * VOCAB];

// ------------------------- helpers ----------------------------------------
__device__ __forceinline__ float gelu_tanh(float x) {
    const float c = 0.7978845608028654f;   // sqrt(2/pi)
    float x3 = x * x * x;
    return 0.5f * x * (1.0f + tanhf(c * (x + 0.044715f * x3)));
}

__device__ __forceinline__ uint32_t f2tf(float f) {
    uint32_t u;
    asm("cvt.rna.tf32.f32 %0, %1;" : "=r"(u) : "f"(f));
    return u;
}

__device__ __forceinline__ void mma_tf32(float* c, const uint32_t* a, const uint32_t* b) {
    asm volatile(
        "mma.sync.aligned.m16n8k8.row.col.f32.tf32.tf32.f32 "
        "{%0,%1,%2,%3}, {%4,%5,%6,%7}, {%8,%9}, {%0,%1,%2,%3};\n"
        : "+f"(c[0]), "+f"(c[1]), "+f"(c[2]), "+f"(c[3])
        : "r"(a[0]), "r"(a[1]), "r"(a[2]), "r"(a[3]), "r"(b[0]), "r"(b[1]));
}

// ------------------------- tensor-core GEMM --------------------------------
// C[M,N] = mode0: alpha*A@B + bias
//          mode1: gelu(alpha*A@B + bias)
//          mode2: alpha*A@B + bias + resScale*D     (D has ld = ldc)
// transB: B is [N][K] row-major (computes A @ B^T)
// batched over blockIdx.z with element strides sA/sB/sC/sBias.
// Block tile 128x128x32, 8 warps, warp tile 64x32, m16n8k8 tf32 MMA.
#define TSTR 136   // smem row stride (words); shift of 8 banks/row -> conflict-free frags

__global__ __launch_bounds__(256, 2)
void tgemm_kernel(const float* __restrict__ A, long long sA,
                  const float* __restrict__ B, long long sB,
                  float* __restrict__ C, long long sC,
                  const float* __restrict__ bias, long long sBias,
                  const float* __restrict__ D,
                  int M, int N, int K, int lda, int ldb, int ldc,
                  float alpha, float resScale, int mode, int transB)
{
    long long z = blockIdx.z;
    A += z * sA;
    B += z * sB;
    C += z * sC;
    if (bias) bias += z * sBias;

    __shared__ uint32_t As[32 * TSTR];
    __shared__ uint32_t Bs[32 * TSTR];

    const int tid  = threadIdx.x;
    const int warp = tid >> 5;
    const int lane = tid & 31;
    const int g    = lane >> 2;     // 0..7
    const int tg   = lane & 3;      // 0..3
    const int wm   = (warp & 1) * 64;
    const int wn   = (warp >> 1) * 32;
    const int row0 = blockIdx.y * 128;
    const int col0 = blockIdx.x * 128;

    float acc[4][4][4];
#pragma unroll
    for (int mi = 0; mi < 4; mi++)
#pragma unroll
        for (int ni = 0; ni < 4; ni++)
#pragma unroll
            for (int r = 0; r < 4; r++) acc[mi][ni][r] = 0.0f;

    const int ar  = tid >> 1;            // 0..127 (A row / B-trans n-row)
    const int akq = (tid & 1) * 16;      // 0 or 16
    const int bkr = tid >> 3;            // 0..31  (B k-row, normal)
    const int bnq = (tid & 7) * 16;      // 0..112

    for (int k0 = 0; k0 < K; k0 += 32) {
        // ---- load A tile: As[k][m] ----
        {
            const float* Ap = A + (long long)(row0 + ar) * lda + k0 + akq;
            bool full = (k0 + akq + 16 <= K) && ((((uintptr_t)Ap) & 15) == 0);
            if (full) {
#pragma unroll
                for (int j4 = 0; j4 < 4; j4++) {
                    float4 v = *(const float4*)(Ap + j4 * 4);
                    int kb = (akq + j4 * 4) * TSTR + ar;
                    As[kb]            = f2tf(v.x);
                    As[kb + TSTR]     = f2tf(v.y);
                    As[kb + 2 * TSTR] = f2tf(v.z);
                    As[kb + 3 * TSTR] = f2tf(v.w);
                }
            } else {
#pragma unroll
                for (int j = 0; j < 16; j++) {
                    int gk = k0 + akq + j;
                    float v = (gk < K) ? Ap[j] : 0.0f;
                    As[(akq + j) * TSTR + ar] = f2tf(v);
                }
            }
        }
        // ---- load B tile: Bs[k][n] ----
        if (!transB) {
            const float* Bp = B + (long long)(k0 + bkr) * ldb + col0 + bnq;
            bool kok = (k0 + bkr) < K;
            bool full = kok && (col0 + bnq + 16 <= N) && ((((uintptr_t)Bp) & 15) == 0);
            if (full) {
#pragma unroll
                for (int j4 = 0; j4 < 4; j4++) {
                    float4 v = *(const float4*)(Bp + j4 * 4);
                    int nb = bkr * TSTR + bnq + j4 * 4;
                    Bs[nb]     = f2tf(v.x);
                    Bs[nb + 1] = f2tf(v.y);
                    Bs[nb + 2] = f2tf(v.z);
                    Bs[nb + 3] = f2tf(v.w);
                }
            } else {
#pragma unroll
                for (int j = 0; j < 16; j++) {
                    int gn = col0 + bnq + j;
                    float v = (kok && gn < N) ? Bp[j] : 0.0f;
                    Bs[bkr * TSTR + bnq + j] = f2tf(v);
                }
            }
        } else {
            // B is [N][K]; need Bs[k][n] = B[n][k]
            const float* Bp = B + (long long)(col0 + ar) * ldb + k0 + akq;
            bool nok = (col0 + ar) < N;
            bool full = nok && (k0 + akq + 16 <= K) && ((((uintptr_t)Bp) & 15) == 0);
            if (full) {
#pragma unroll
                for (int j4 = 0; j4 < 4; j4++) {
                    float4 v = *(const float4*)(Bp + j4 * 4);
                    int kb = (akq + j4 * 4) * TSTR + ar;
                    Bs[kb]            = f2tf(v.x);
                    Bs[kb + TSTR]     = f2tf(v.y);
                    Bs[kb + 2 * TSTR] = f2tf(v.z);
                    Bs[kb + 3 * TSTR] = f2tf(v.w);
                }
            } else {
#pragma unroll
                for (int j = 0; j < 16; j++) {
                    int gk = k0 + akq + j;
                    float v = (nok && gk < K) ? Bp[j] : 0.0f;
                    Bs[(akq + j) * TSTR + ar] = f2tf(v);
                }
            }
        }
        __syncthreads();

#pragma unroll
        for (int ks = 0; ks < 4; ks++) {
            const int kk = ks * 8;
            uint32_t af[4][4];
            uint32_t bf[4][2];
#pragma unroll
            for (int mi = 0; mi < 4; mi++) {
                int m0 = wm + mi * 16 + g;
                af[mi][0] = As[(kk + tg) * TSTR + m0];
                af[mi][1] = As[(kk + tg) * TSTR + m0 + 8];
                af[mi][2] = As[(kk + tg + 4) * TSTR + m0];
                af[mi][3] = As[(kk + tg + 4) * TSTR + m0 + 8];
            }
#pragma unroll
            for (int ni = 0; ni < 4; ni++) {
                int n0 = wn + ni * 8 + g;
                bf[ni][0] = Bs[(kk + tg) * TSTR + n0];
                bf[ni][1] = Bs[(kk + tg + 4) * TSTR + n0];
            }
#pragma unroll
            for (int mi = 0; mi < 4; mi++)
#pragma unroll
                for (int ni = 0; ni < 4; ni++)
                    mma_tf32(acc[mi][ni], af[mi], bf[ni]);
        }
        __syncthreads();
    }

    // ---- epilogue ----
#pragma unroll
    for (int mi = 0; mi < 4; mi++) {
#pragma unroll
        for (int rr = 0; rr < 2; rr++) {
            int grow = row0 + wm + mi * 16 + g + rr * 8;
            if (grow >= M) continue;
#pragma unroll
            for (int ni = 0; ni < 4; ni++) {
                int gcol = col0 + wn + ni * 8 + tg * 2;
#pragma unroll
                for (int q = 0; q < 2; q++) {
                    int gc = gcol + q;
                    if (gc >= N) continue;
                    float v = alpha * acc[mi][ni][rr * 2 + q];
                    if (bias) v += bias[gc];
                    if (mode == 1) v = gelu_tanh(v);
                    if (mode == 2) v += resScale * D[(long long)grow * ldc + gc];
                    C[(long long)grow * ldc + gc] = v;
                }
            }
        }
    }
}

// ------------------------- layernorm (one block per row) --------------------
__global__ void layernorm_kernel(const float* __restrict__ in, float* __restrict__ out,
                                 const float* __restrict__ gamma, const float* __restrict__ beta)
{
    int row = blockIdx.x;
    const float* x = in + (long long)row * DE;
    float s = 0.f, s2 = 0.f;
    for (int i = threadIdx.x; i < DE; i += 256) { float v = x[i]; s += v; s2 += v * v; }
    __shared__ float sh1[256], sh2[256];
    sh1[threadIdx.x] = s; sh2[threadIdx.x] = s2;
    __syncthreads();
    for (int off = 128; off > 0; off >>= 1) {
        if (threadIdx.x < off) {
            sh1[threadIdx.x] += sh1[threadIdx.x + off];
            sh2[threadIdx.x] += sh2[threadIdx.x + off];
        }
        __syncthreads();
    }
    float mean = sh1[0] / DE;
    float var  = fmaxf(sh2[0] / DE - mean * mean, 0.0f);
    float sd   = sqrtf(var);
    float inv  = (sd == 0.0f) ? 1.0f : 1.0f / sd;
    float* o = out + (long long)row * DE;
    for (int i = threadIdx.x; i < DE; i += 256)
        o[i] = gamma[i] * ((x[i] - mean) * inv) + beta[i];
}

// ------------------------- row softmax (in may equal out) -------------------
__global__ void softmax_kernel(const float* __restrict__ in, float* __restrict__ out, int N)
{
    long long row = blockIdx.x;
    const float* x = in + row * (long long)N;
    float* o = out + row * (long long)N;
    __shared__ float sh[256];
    float m = -3.4e38f;
    for (int i = threadIdx.x; i < N; i += 256) m = fmaxf(m, x[i]);
    sh[threadIdx.x] = m;
    __syncthreads();
    for (int off = 128; off > 0; off >>= 1) {
        if (threadIdx.x < off) sh[threadIdx.x] = fmaxf(sh[threadIdx.x], sh[threadIdx.x + off]);
        __syncthreads();
    }
    m = sh[0];
    __syncthreads();
    float s = 0.f;
    for (int i = threadIdx.x; i < N; i += 256) {
        float e = expf(x[i] - m);
        o[i] = e;
        s += e;
    }
    sh[threadIdx.x] = s;
    __syncthreads();
    for (int off = 128; off > 0; off >>= 1) {
        if (threadIdx.x < off) sh[threadIdx.x] += sh[threadIdx.x + off];
        __syncthreads();
    }
    float invs = 1.0f / sh[0];
    for (int i = threadIdx.x; i < N; i += 256) o[i] *= invs;
}

// ------------------------- attn gemv: y[:,h] = P_h @ vsel[:,h], h<11 --------
__global__ void attn_gemv_kernel(const float* __restrict__ S, const float* __restrict__ vsel,
                                 float* __restrict__ y)
{
    int h = blockIdx.z;        // 0..10
    int row = blockIdx.x;      // 0..L-1
    const float* p = S + ((long long)h * L + row) * L;
    float s = 0.f;
    for (int mi = threadIdx.x; mi < L; mi += 256)
        s += p[mi] * vsel[(long long)mi * YCOLS + h];
    __shared__ float sh[256];
    sh[threadIdx.x] = s;
    __syncthreads();
    for (int off = 128; off > 0; off >>= 1) {
        if (threadIdx.x < off) sh[threadIdx.x] += sh[threadIdx.x + off];
        __syncthreads();
    }
    if (threadIdx.x == 0) y[(long long)row * YCOLS + h] = sh[0];
}

// ------------------------- misc -------------------------------------------
__global__ void embed_kernel(const int* __restrict__ x, const float* __restrict__ we,
                             const float* __restrict__ pe, float* __restrict__ Y)
{
    int i = blockIdx.x * blockDim.x + threadIdx.x;
    if (i >= L * DE) return;
    int l = i / DE, d = i % DE;
    Y[i] = we[(long long)x[l] * DE + d] + pe[i];
}

__global__ void pack_wv_kernel(const float* __restrict__ Wv, const float* __restrict__ bv,
                               float* __restrict__ Wsel, float* __restrict__ bsel, int layer)
{
    int i = blockIdx.x * blockDim.x + threadIdx.x;
    if (i < DE * NSEL) {
        int d = i / NSEL, c = i % NSEL;
        int h  = (c < NH - 1) ? c : (NH - 1);
        int vc = (c < NH - 1) ? 0 : (c - (NH - 1));
        Wsel[(long long)d * YCOLS + c] =
            Wv[(((long long)layer * NH + h) * DE + d) * DV + vc];
    }
    if (i < NSEL) {
        int h  = (i < NH - 1) ? i : (NH - 1);
        int vc = (i < NH - 1) ? 0 : (i - (NH - 1));
        bsel[i] = bv[((long long)layer * NH + h) * DV + vc];
    }
}

__global__ void add_kernel(const float* __restrict__ a, const float* __restrict__ b,
                           float* __restrict__ c)
{
    int i = blockIdx.x * blockDim.x + threadIdx.x;
    if (i < L * DE) c[i] = a[i] + b[i];
}

// ------------------------- host side ---------------------------------------
static void gemm(const float* A, long long sA, const float* B, long long sB,
                 float* C, long long sC, const float* bias, long long sBias,
                 const float* D, int M, int N, int K, int lda, int ldb, int ldc,
                 float alpha, float resScale, int mode, int transB, int batch)
{
    dim3 grid((N + 127) / 128, (M + 127) / 128, batch);
    tgemm_kernel<<<grid, 256>>>(A, sA, B, sB, C, sC, bias, sBias, D,
                                M, N, K, lda, ldb, ldc, alpha, resScale, mode, transB);
}

template <typename T>
static float* sym_addr(T& sym)
{
    void* p = nullptr;
    cudaGetSymbolAddress(&p, sym);
    return (float*)p;
}

extern "C" void kernel_launch(void* const* d_in, const int* in_sizes, int n_in,
                              void* d_out, int out_size)
{
    const int*   x   = (const int*)  d_in[0];
    const float* we  = (const float*)d_in[1];
    const float* pe  = (const float*)d_in[2];
    const float* Wq  = (const float*)d_in[3];
    const float* bq  = (const float*)d_in[4];
    const float* Wk  = (const float*)d_in[5];
    const float* bk  = (const float*)d_in[6];
    const float* Wv  = (const float*)d_in[7];
    const float* bv  = (const float*)d_in[8];
    const float* Wo  = (const float*)d_in[9];
    const float* bo  = (const float*)d_in[10];
    const float* g1  = (const float*)d_in[11];
    const float* be1 = (const float*)d_in[12];
    const float* g2  = (const float*)d_in[13];
    const float* be2 = (const float*)d_in[14];
    const float* W1  = (const float*)d_in[15];
    const float* bm1 = (const float*)d_in[16];
    const float* W2  = (const float*)d_in[17];
    const float* bm2 = (const float*)d_in[18];
    const float* gf  = (const float*)d_in[19];
    const float* bef = (const float*)d_in[20];
    const float* Wu  = (const float*)d_in[21];
    const float* bu  = (const float*)d_in[22];
    float* out = (float*)d_out;

    float* Y    = sym_addr(g_Y);
    float* xn   = sym_addr(g_xn);
    float* zn   = sym_addr(g_zn);
    float* R    = sym_addr(g_R);
    float* Qb   = sym_addr(g_Qb);
    float* Kb   = sym_addr(g_Kb);
    float* S    = sym_addr(g_S);
    float* vsel = sym_addr(g_vsel);
    float* Wsel = sym_addr(g_Wsel);
    float* bsel = sym_addr(g_bsel);
    float* ya   = sym_addr(g_yattn);
    float* mlp  = sym_addr(g_mlp);
    float* lg   = sym_addr(g_logits);

    const float inv_sqrt_de = 0.03608439182435161f;  // 1/sqrt(768)

    embed_kernel<<<(L * DE + 255) / 256, 256>>>(x, we, pe, Y);

    for (int l = 0; l < NLAYERS; l++) {
        // xn = LN(Y; g1, be1)
        layernorm_kernel<<<L, 256>>>(Y, xn, g1 + l * DE, be1 + l * DE);

        // Q, K projections, batched over heads
        gemm(xn, 0, Wq + (long long)l * NH * DE * DE, (long long)DE * DE,
             Qb, (long long)L * DE, bq + (long long)l * NH * DE, DE, nullptr,
             L, DE, DE, DE, DE, DE, 1.0f, 0.0f, 0, 0, NH);
        gemm(xn, 0, Wk + (long long)l * NH * DE * DE, (long long)DE * DE,
             Kb, (long long)L * DE, bk + (long long)l * NH * DE, DE, nullptr,
             L, DE, DE, DE, DE, DE, 1.0f, 0.0f, 0, 0, NH);

        // packed V projection: only columns that survive the overlapping writes
        pack_wv_kernel<<<(DE * NSEL + 255) / 256, 256>>>(Wv, bv, Wsel, bsel, l);
        gemm(xn, 0, Wsel, 0, vsel, 0, bsel, 0, nullptr,
             L, NSEL, DE, DE, YCOLS, YCOLS, 1.0f, 0.0f, 0, 0, 1);

        // scores = Q @ K^T / sqrt(DE), batched (transB: K stays row-major)
        gemm(Qb, (long long)L * DE, Kb, (long long)L * DE,
             S, (long long)L * L, nullptr, 0, nullptr,
             L, L, DE, DE, DE, L, inv_sqrt_de, 0.0f, 0, 1, NH);

        // row softmax over all heads
        softmax_kernel<<<NH * L, 256>>>(S, S, L);

        // attn: heads 0..10 need only column 0 of V -> gemv into y[:,h]
        attn_gemv_kernel<<<dim3(L, 1, NH - 1), 256>>>(S, vsel, ya);
        // head 11: full 64-wide GEMM into y[:,11:75]
        gemm(S + (long long)(NH - 1) * L * L, 0, vsel + (NH - 1), 0,
             ya + (NH - 1), 0, nullptr, 0, nullptr,
             L, DV, L, L, YCOLS, YCOLS, 1.0f, 0.0f, 0, 0, 1);

        // Y = 2*Y + (y @ Wo + bo), K = 75 (rest of y is zero)
        gemm(ya, 0, Wo + (long long)l * DE * DE, 0, Y, 0,
             bo + l * DE, 0, Y,
             L, DE, NSEL, YCOLS, DE, DE, 1.0f, 2.0f, 2, 0, 1);

        // zn = LN(Y; g2, be2)
        layernorm_kernel<<<L, 256>>>(Y, zn, g2 + l * DE, be2 + l * DE);

        // mlp = gelu(zn @ W1 + bm1)
        gemm(zn, 0, W1 + (long long)l * DE * DMLP, 0, mlp, 0,
             bm1 + (long long)l * DMLP, 0, nullptr,
             L, DMLP, DE, DE, DMLP, DMLP, 1.0f, 0.0f, 1, 0, 1);

        // R = Y + zn ;  Y = R + (mlp @ W2 + bm2)
        add_kernel<<<(L * DE + 255) / 256, 256>>>(Y, zn, R);
        gemm(mlp, 0, W2 + (long long)l * DMLP * DE, 0, Y, 0,
             bm2 + l * DE, 0, R,
             L, DE, DMLP, DMLP, DE, DE, 1.0f, 1.0f, 2, 0, 1);
    }

    // final LN + vocab projection + softmax -> out
    layernorm_kernel<<<L, 256>>>(Y, xn, gf, bef);
    gemm(xn, 0, Wu, 0, lg, 0, bu, 0, nullptr,
         L, VOCAB, DE, DE, VOCAB, VOCAB, 1.0f, 0.0f, 0, 0, 1);
    softmax_kernel<<<L, 256>>>(lg, out, VOCAB);
}

// round 5
// speedup vs baseline: 5.7339x; 2.3958x over previous
#include <cuda_runtime.h>
#include <cuda_bf16.h>
#include <math.h>
#include <stdint.h>

#define L 2048
#define DE 768
#define DV 64
#define NH 12
#define DMLP 3072
#define VOCAB 32000
#define NLAYERS 4
#define NSEL 75     // 11 head-col0 + 64 cols of head 11
#define YCOLS 80    // padded K for Wo GEMM

typedef __nv_bfloat16 bf16;

// ------------------------- device scratch ----------------------------------
__device__ __align__(256) float g_Y[L * DE];
__device__ __align__(256) float g_zn[L * DE];
__device__ __align__(256) float g_R[L * DE];
__device__ __align__(256) bf16  g_xnb[L * DE];
__device__ __align__(256) bf16  g_znb[L * DE];
__device__ __align__(256) bf16  g_Qb[NH * L * DE];
__device__ __align__(256) bf16  g_Kb[NH * L * DE];
__device__ __align__(256) bf16  g_S[NH * L * L];
__device__ __align__(256) bf16  g_vselT[YCOLS * L];
__device__ __align__(256) bf16  g_WselT[YCOLS * DE];
__device__ __align__(256) float g_bsel[YCOLS];
__device__ __align__(256) bf16  g_ya[L * YCOLS];
__device__ __align__(256) bf16  g_mlp[L * DMLP];
__device__ __align__(256) bf16  g_logits[L * VOCAB];
// bf16 transposed weights: [n][k]
__device__ __align__(256) bf16  g_Wqb[NLAYERS * NH * DE * DE];
__device__ __align__(256) bf16  g_Wkb[NLAYERS * NH * DE * DE];
__device__ __align__(256) bf16  g_Wob[NLAYERS * DE * YCOLS];
__device__ __align__(256) bf16  g_W1b[NLAYERS * DMLP * DE];
__device__ __align__(256) bf16  g_W2b[NLAYERS * DE * DMLP];
__device__ __align__(256) bf16  g_Wub[(long long)VOCAB * DE];

// ------------------------- helpers ----------------------------------------
__device__ __forceinline__ float gelu_tanh(float x) {
    const float c = 0.7978845608028654f;   // sqrt(2/pi)
    float x3 = x * x * x;
    return 0.5f * x * (1.0f + tanhf(c * (x + 0.044715f * x3)));
}

__device__ __forceinline__ void mma_bf16(float* c, const uint32_t* a, const uint32_t* b) {
    asm volatile(
        "mma.sync.aligned.m16n8k16.row.col.f32.bf16.bf16.f32 "
        "{%0,%1,%2,%3}, {%4,%5,%6,%7}, {%8,%9}, {%0,%1,%2,%3};\n"
        : "+f"(c[0]), "+f"(c[1]), "+f"(c[2]), "+f"(c[3])
        : "r"(a[0]), "r"(a[1]), "r"(a[2]), "r"(a[3]), "r"(b[0]), "r"(b[1]));
}

__device__ __forceinline__ void ldsm4(uint32_t* d, uint32_t addr) {
    asm volatile("ldmatrix.sync.aligned.m8n8.x4.shared.b16 {%0,%1,%2,%3}, [%4];"
                 : "=r"(d[0]), "=r"(d[1]), "=r"(d[2]), "=r"(d[3]) : "r"(addr));
}

__device__ __forceinline__ void cpasync16(uint32_t dst, const void* src, int sz) {
    asm volatile("cp.async.cg.shared.global [%0], [%1], 16, %2;\n"
                 :: "r"(dst), "l"(src), "r"(sz));
}

// ------------------------- bf16 tensor-core GEMM ----------------------------
// C[M,N] = epilogue(alpha * A @ B^T + bias [+ resScale*D])
// A: [M][lda] bf16 row-major. B: [N][ldb] bf16 row-major (i.e. already "transposed").
// mode: 0 = bias, 1 = gelu(bias), 2 = bias + resScale*D (D fp32, ld=ldc)
// outBf16: C stored as bf16 (ldc elems) else fp32.
// transC: C stored transposed: Cb[gcol*ldct + grow] (bf16 only).
// Block 128x128x32, 8 warps (warp 64x32), m16n8k16, ldmatrix, cp.async 2-stage.
#define BKPAD 40            // bf16 elems per smem row (80 bytes -> conflict-free LDSM)
#define BUFB  (128 * BKPAD * 2)  // bytes per stage buffer

__global__ __launch_bounds__(256, 2)
void hgemm_kernel(const bf16* __restrict__ A, long long sA,
                  const bf16* __restrict__ B, long long sB,
                  void* __restrict__ Cv, long long sC,
                  const float* __restrict__ bias, long long sBias,
                  const float* __restrict__ D,
                  int M, int N, int K, int lda, int ldb, int ldc,
                  float alpha, float resScale, int mode,
                  int outBf16, int transC, int ldct)
{
    long long z = blockIdx.z;
    A += z * sA;
    B += z * sB;
    if (bias) bias += z * sBias;

    __shared__ __align__(16) bf16 As[2][128 * BKPAD];
    __shared__ __align__(16) bf16 Bs[2][128 * BKPAD];

    const int tid  = threadIdx.x;
    const int warp = tid >> 5;
    const int lane = tid & 31;
    const int g    = lane >> 2;
    const int tg   = lane & 3;
    const int q8   = lane >> 3;     // 0..3 (ldmatrix address group)
    const int r8   = lane & 7;
    const int wm   = (warp & 1) * 64;
    const int wn   = (warp >> 1) * 32;
    const int row0 = blockIdx.y * 128;
    const int col0 = blockIdx.x * 128;

    const uint32_t asBase = (uint32_t)__cvta_generic_to_shared(&As[0][0]);
    const uint32_t bsBase = (uint32_t)__cvta_generic_to_shared(&Bs[0][0]);

    float acc[4][4][4];
#pragma unroll
    for (int mi = 0; mi < 4; mi++)
#pragma unroll
        for (int ni = 0; ni < 4; ni++)
#pragma unroll
            for (int r = 0; r < 4; r++) acc[mi][ni][r] = 0.0f;

    const int nT = (K + 31) / 32;

    // ---- tile loader (cp.async, 16B chunks, zero-fill OOB) ----
    auto load_tile = [&](int kt, int buf) {
        const int k0 = kt * 32;
#pragma unroll
        for (int i = 0; i < 2; i++) {
            int c = tid + i * 256;          // 512 chunks
            int row = c >> 2, ch = c & 3;
            int gk = k0 + ch * 8;
            int grow = row0 + row;
            const bf16* src = A + (long long)grow * lda + gk;
            int sz = (grow < M && gk + 8 <= K) ? 16 : 0;
            if (!sz) src = A;
            cpasync16(asBase + buf * BUFB + row * 80 + ch * 16, src, sz);
        }
#pragma unroll
        for (int i = 0; i < 2; i++) {
            int c = tid + i * 256;
            int row = c >> 2, ch = c & 3;
            int gk = k0 + ch * 8;
            int gn = col0 + row;
            const bf16* src = B + (long long)gn * ldb + gk;
            int sz = (gn < N && gk + 8 <= K) ? 16 : 0;
            if (!sz) src = B;
            cpasync16(bsBase + buf * BUFB + row * 80 + ch * 16, src, sz);
        }
    };

    load_tile(0, 0);
    asm volatile("cp.async.commit_group;\n");

    const int aMoff = ((q8 & 1) ? 8 : 0) + r8;   // A: q1,q3 -> +8 rows
    const int aKoff = (q8 & 2) ? 8 : 0;          // A: q2,q3 -> +8 k
    const int bNoff = ((q8 & 2) ? 8 : 0) + r8;   // B: q2,q3 -> +8 n-rows
    const int bKoff = (q8 & 1) ? 8 : 0;          // B: q1,q3 -> +8 k

    for (int kt = 0; kt < nT; kt++) {
        asm volatile("cp.async.wait_group 0;\n");
        __syncthreads();
        if (kt + 1 < nT) {
            load_tile(kt + 1, (kt + 1) & 1);
            asm volatile("cp.async.commit_group;\n");
        }
        const uint32_t aB = asBase + (kt & 1) * BUFB;
        const uint32_t bB = bsBase + (kt & 1) * BUFB;
#pragma unroll
        for (int ks = 0; ks < 2; ks++) {
            const int kk = ks * 16;
            uint32_t af[4][4];
            uint32_t bfr[4][2];
#pragma unroll
            for (int mi = 0; mi < 4; mi++)
                ldsm4(af[mi], aB + (wm + mi * 16 + aMoff) * 80 + (kk + aKoff) * 2);
#pragma unroll
            for (int np = 0; np < 2; np++) {
                uint32_t t4[4];
                ldsm4(t4, bB + (wn + np * 16 + bNoff) * 80 + (kk + bKoff) * 2);
                bfr[2 * np][0] = t4[0]; bfr[2 * np][1] = t4[1];
                bfr[2 * np + 1][0] = t4[2]; bfr[2 * np + 1][1] = t4[3];
            }
#pragma unroll
            for (int mi = 0; mi < 4; mi++)
#pragma unroll
                for (int ni = 0; ni < 4; ni++)
                    mma_bf16(acc[mi][ni], af[mi], bfr[ni]);
        }
        __syncthreads();
    }

    // ---- epilogue ----
#pragma unroll
    for (int mi = 0; mi < 4; mi++) {
#pragma unroll
        for (int rr = 0; rr < 2; rr++) {
            int grow = row0 + wm + mi * 16 + g + rr * 8;
            if (grow >= M) continue;
#pragma unroll
            for (int ni = 0; ni < 4; ni++) {
#pragma unroll
                for (int qq = 0; qq < 2; qq++) {
                    int gcol = col0 + wn + ni * 8 + tg * 2 + qq;
                    if (gcol >= N) continue;
                    float v = alpha * acc[mi][ni][rr * 2 + qq];
                    if (bias) v += bias[gcol];
                    if (mode == 1) v = gelu_tanh(v);
                    if (mode == 2) v += resScale * D[(long long)grow * ldc + gcol];
                    if (transC) {
                        ((bf16*)Cv)[(long long)gcol * ldct + grow] = __float2bfloat16(v);
                    } else if (outBf16) {
                        ((bf16*)Cv)[(z * sC) + (long long)grow * ldc + gcol] = __float2bfloat16(v);
                    } else {
                        ((float*)Cv)[(z * sC) + (long long)grow * ldc + gcol] = v;
                    }
                }
            }
        }
    }
}

// ------------------------- transpose + convert: W[K][N] -> Wb[N][Kpad] ------
__global__ void tconv_kernel(const float* __restrict__ in, bf16* __restrict__ out,
                             int Ksrc, int N, int Kpad,
                             long long inStride, long long outStride)
{
    long long zb = blockIdx.z;
    in  += zb * inStride;
    out += zb * outStride;
    __shared__ float tile[32][33];
    int k0 = blockIdx.x * 32, n0 = blockIdx.y * 32;
    int tx = threadIdx.x, ty = threadIdx.y;   // 32 x 8
#pragma unroll
    for (int i = 0; i < 32; i += 8) {
        int k = k0 + ty + i, n = n0 + tx;
        tile[ty + i][tx] = (k < Ksrc && n < N) ? in[(long long)k * N + n] : 0.0f;
    }
    __syncthreads();
#pragma unroll
    for (int i = 0; i < 32; i += 8) {
        int n = n0 + ty + i, k = k0 + tx;
        if (n < N && k < Kpad)
            out[(long long)n * Kpad + k] = __float2bfloat16(tile[tx][ty + i]);
    }
}

// ------------------------- layernorm ---------------------------------------
__global__ void ln_kernel(const float* __restrict__ in, bf16* __restrict__ outB,
                          float* __restrict__ outF,
                          const float* __restrict__ gamma, const float* __restrict__ beta)
{
    int row = blockIdx.x;
    const float* x = in + (long long)row * DE;
    float s = 0.f, s2 = 0.f;
    for (int i = threadIdx.x; i < DE; i += 256) { float v = x[i]; s += v; s2 += v * v; }
    __shared__ float sh1[256], sh2[256];
    sh1[threadIdx.x] = s; sh2[threadIdx.x] = s2;
    __syncthreads();
    for (int off = 128; off > 0; off >>= 1) {
        if (threadIdx.x < off) {
            sh1[threadIdx.x] += sh1[threadIdx.x + off];
            sh2[threadIdx.x] += sh2[threadIdx.x + off];
        }
        __syncthreads();
    }
    float mean = sh1[0] / DE;
    float var  = fmaxf(sh2[0] / DE - mean * mean, 0.0f);
    float sd   = sqrtf(var);
    float inv  = (sd == 0.0f) ? 1.0f : 1.0f / sd;
    for (int i = threadIdx.x; i < DE; i += 256) {
        float v = gamma[i] * ((x[i] - mean) * inv) + beta[i];
        outB[(long long)row * DE + i] = __float2bfloat16(v);
        if (outF) outF[(long long)row * DE + i] = v;
    }
}

// ------------------------- softmax: bf16 rows of 2048, in-place -------------
__global__ void softmax2048_kernel(bf16* __restrict__ S)
{
    long long row = blockIdx.x;
    uint4* p = (uint4*)(S + row * L);
    int t = threadIdx.x;                 // 256, one uint4 (8 bf16) each
    uint4 v = p[t];
    __nv_bfloat162 h2[4];
    *(uint4*)h2 = v;
    float f[8];
#pragma unroll
    for (int i = 0; i < 4; i++) {
        float2 d = __bfloat1622float2(h2[i]);
        f[2 * i] = d.x; f[2 * i + 1] = d.y;
    }
    __shared__ float sh[256];
    float m = f[0];
#pragma unroll
    for (int i = 1; i < 8; i++) m = fmaxf(m, f[i]);
    sh[t] = m; __syncthreads();
    for (int off = 128; off > 0; off >>= 1) {
        if (t < off) sh[t] = fmaxf(sh[t], sh[t + off]);
        __syncthreads();
    }
    m = sh[0]; __syncthreads();
    float s = 0.f;
#pragma unroll
    for (int i = 0; i < 8; i++) { f[i] = expf(f[i] - m); s += f[i]; }
    sh[t] = s; __syncthreads();
    for (int off = 128; off > 0; off >>= 1) {
        if (t < off) sh[t] += sh[t + off];
        __syncthreads();
    }
    float invs = 1.0f / sh[0];
#pragma unroll
    for (int i = 0; i < 4; i++)
        h2[i] = __floats2bfloat162_rn(f[2 * i] * invs, f[2 * i + 1] * invs);
    p[t] = *(uint4*)h2;
}

// ------------------------- final softmax: bf16 in, fp32 out -----------------
__global__ void softmax_vocab_kernel(const bf16* __restrict__ in, float* __restrict__ out)
{
    long long row = blockIdx.x;
    const bf16* x = in + row * VOCAB;
    float* o = out + row * VOCAB;
    __shared__ float sh[256];
    int t = threadIdx.x;
    float m = -3.4e38f;
    for (int i = t; i < VOCAB; i += 256) m = fmaxf(m, __bfloat162float(x[i]));
    sh[t] = m; __syncthreads();
    for (int off = 128; off > 0; off >>= 1) {
        if (t < off) sh[t] = fmaxf(sh[t], sh[t + off]);
        __syncthreads();
    }
    m = sh[0]; __syncthreads();
    float s = 0.f;
    for (int i = t; i < VOCAB; i += 256) {
        float e = expf(__bfloat162float(x[i]) - m);
        o[i] = e; s += e;
    }
    sh[t] = s; __syncthreads();
    for (int off = 128; off > 0; off >>= 1) {
        if (t < off) sh[t] += sh[t + off];
        __syncthreads();
    }
    float invs = 1.0f / sh[0];
    for (int i = t; i < VOCAB; i += 256) o[i] *= invs;
}

// ------------------------- attn gemv: ya[:,h] = P_h @ vT[h,:], h<11 ---------
__global__ void attn_gemv_kernel(const bf16* __restrict__ S, const bf16* __restrict__ vT,
                                 bf16* __restrict__ ya)
{
    int h = blockIdx.z;        // 0..10
    int row = blockIdx.x;
    const uint4* p  = (const uint4*)(S + ((long long)h * L + row) * L);
    const uint4* vp = (const uint4*)(vT + (long long)h * L);
    int t = threadIdx.x;
    uint4 a = p[t], b = vp[t];
    __nv_bfloat162 a2[4], b2[4];
    *(uint4*)a2 = a; *(uint4*)b2 = b;
    float s = 0.f;
#pragma unroll
    for (int i = 0; i < 4; i++) {
        float2 fa = __bfloat1622float2(a2[i]);
        float2 fb = __bfloat1622float2(b2[i]);
        s += fa.x * fb.x + fa.y * fb.y;
    }
    __shared__ float sh[256];
    sh[t] = s; __syncthreads();
    for (int off = 128; off > 0; off >>= 1) {
        if (t < off) sh[t] += sh[t + off];
        __syncthreads();
    }
    if (t == 0) ya[(long long)row * YCOLS + h] = __float2bfloat16(sh[0]);
}

// ------------------------- misc --------------------------------------------
__global__ void embed_kernel(const int* __restrict__ x, const float* __restrict__ we,
                             const float* __restrict__ pe, float* __restrict__ Y)
{
    int i = blockIdx.x * blockDim.x + threadIdx.x;
    if (i >= L * DE) return;
    int l = i / DE, d = i % DE;
    Y[i] = we[(long long)x[l] * DE + d] + pe[i];
}

// WselT[c][d] (bf16, [YCOLS][DE], zero-padded rows 75..79) + bsel fp32
__global__ void pack_wsel_kernel(const float* __restrict__ Wv, const float* __restrict__ bv,
                                 bf16* __restrict__ WselT, float* __restrict__ bsel, int layer)
{
    int i = blockIdx.x * blockDim.x + threadIdx.x;
    if (i < YCOLS * DE) {
        int c = i / DE, d = i % DE;
        float v = 0.0f;
        if (c < NSEL) {
            int h  = (c < NH - 1) ? c : (NH - 1);
            int vc = (c < NH - 1) ? 0 : (c - (NH - 1));
            v = Wv[(((long long)layer * NH + h) * DE + d) * DV + vc];
        }
        WselT[i] = __float2bfloat16(v);
    }
    if (i < YCOLS) {
        float v = 0.0f;
        if (i < NSEL) {
            int h  = (i < NH - 1) ? i : (NH - 1);
            int vc = (i < NH - 1) ? 0 : (i - (NH - 1));
            v = bv[((long long)layer * NH + h) * DV + vc];
        }
        bsel[i] = v;
    }
}

__global__ void zero_ya_pad_kernel(bf16* __restrict__ ya)
{
    int i = blockIdx.x * blockDim.x + threadIdx.x;
    if (i >= L * (YCOLS - NSEL)) return;
    int row = i / (YCOLS - NSEL), j = i % (YCOLS - NSEL);
    ya[(long long)row * YCOLS + NSEL + j] = __float2bfloat16(0.0f);
}

__global__ void add_kernel(const float* __restrict__ a, const float* __restrict__ b,
                           float* __restrict__ c)
{
    int i = blockIdx.x * blockDim.x + threadIdx.x;
    if (i < L * DE) c[i] = a[i] + b[i];
}

// ------------------------- host side ---------------------------------------
static void gemm(const bf16* A, long long sA, const bf16* B, long long sB,
                 void* C, long long sC, const float* bias, long long sBias,
                 const float* D, int M, int N, int K, int lda, int ldb, int ldc,
                 float alpha, float resScale, int mode, int outBf16, int transC,
                 int ldct, int batch)
{
    dim3 grid((N + 127) / 128, (M + 127) / 128, batch);
    hgemm_kernel<<<grid, 256>>>(A, sA, B, sB, C, sC, bias, sBias, D,
                                M, N, K, lda, ldb, ldc, alpha, resScale, mode,
                                outBf16, transC, ldct);
}

static void tconv(const float* in, bf16* out, int Ksrc, int N, int Kpad,
                  long long inStride, long long outStride, int batch)
{
    dim3 grid((Kpad + 31) / 32, (N + 31) / 32, batch);
    tconv_kernel<<<grid, dim3(32, 8)>>>(in, out, Ksrc, N, Kpad, inStride, outStride);
}

template <typename T>
static T* sym_addr(T* sym)
{
    void* p = nullptr;
    cudaGetSymbolAddress(&p, (const void*)sym);
    return (T*)p;
}

extern "C" void kernel_launch(void* const* d_in, const int* in_sizes, int n_in,
                              void* d_out, int out_size)
{
    const int*   x   = (const int*)  d_in[0];
    const float* we  = (const float*)d_in[1];
    const float* pe  = (const float*)d_in[2];
    const float* Wq  = (const float*)d_in[3];
    const float* bq  = (const float*)d_in[4];
    const float* Wk  = (const float*)d_in[5];
    const float* bk  = (const float*)d_in[6];
    const float* Wv  = (const float*)d_in[7];
    const float* bv  = (const float*)d_in[8];
    const float* Wo  = (const float*)d_in[9];
    const float* bo  = (const float*)d_in[10];
    const float* g1  = (const float*)d_in[11];
    const float* be1 = (const float*)d_in[12];
    const float* g2  = (const float*)d_in[13];
    const float* be2 = (const float*)d_in[14];
    const float* W1  = (const float*)d_in[15];
    const float* bm1 = (const float*)d_in[16];
    const float* W2  = (const float*)d_in[17];
    const float* bm2 = (const float*)d_in[18];
    const float* gf  = (const float*)d_in[19];
    const float* bef = (const float*)d_in[20];
    const float* Wu  = (const float*)d_in[21];
    const float* bu  = (const float*)d_in[22];
    float* out = (float*)d_out;

    float* Y     = sym_addr(g_Y);
    float* zn    = sym_addr(g_zn);
    float* R     = sym_addr(g_R);
    bf16*  xnb   = sym_addr(g_xnb);
    bf16*  znb   = sym_addr(g_znb);
    bf16*  Qb    = sym_addr(g_Qb);
    bf16*  Kb    = sym_addr(g_Kb);
    bf16*  S     = sym_addr(g_S);
    bf16*  vselT = sym_addr(g_vselT);
    bf16*  WselT = sym_addr(g_WselT);
    float* bsel  = sym_addr(g_bsel);
    bf16*  ya    = sym_addr(g_ya);
    bf16*  mlp   = sym_addr(g_mlp);
    bf16*  lg    = sym_addr(g_logits);
    bf16*  Wqb   = sym_addr(g_Wqb);
    bf16*  Wkb   = sym_addr(g_Wkb);
    bf16*  Wob   = sym_addr(g_Wob);
    bf16*  W1b   = sym_addr(g_W1b);
    bf16*  W2b   = sym_addr(g_W2b);
    bf16*  Wub   = sym_addr(g_Wub);

    const float inv_sqrt_de = 0.03608439182435161f;  // 1/sqrt(768)

    // one-time (per call) weight transpose + bf16 conversion
    tconv(Wq, Wqb, DE, DE, DE, (long long)DE * DE, (long long)DE * DE, NLAYERS * NH);
    tconv(Wk, Wkb, DE, DE, DE, (long long)DE * DE, (long long)DE * DE, NLAYERS * NH);
    tconv(Wo, Wob, NSEL, DE, YCOLS, (long long)(NH * DV) * DE, (long long)DE * YCOLS, NLAYERS);
    tconv(W1, W1b, DE, DMLP, DE, (long long)DE * DMLP, (long long)DMLP * DE, NLAYERS);
    tconv(W2, W2b, DMLP, DE, DMLP, (long long)DMLP * DE, (long long)DE * DMLP, NLAYERS);
    tconv(Wu, Wub, DE, VOCAB, DE, 0, 0, 1);

    embed_kernel<<<(L * DE + 255) / 256, 256>>>(x, we, pe, Y);
    zero_ya_pad_kernel<<<(L * (YCOLS - NSEL) + 255) / 256, 256>>>(ya);

    for (int l = 0; l < NLAYERS; l++) {
        // xn = LN(Y; g1, be1) -> bf16
        ln_kernel<<<L, 256>>>(Y, xnb, nullptr, g1 + l * DE, be1 + l * DE);

        // Q, K projections (batched over heads), outputs bf16
        gemm(xnb, 0, Wqb + (long long)l * NH * DE * DE, (long long)DE * DE,
             Qb, (long long)L * DE, bq + (long long)l * NH * DE, DE, nullptr,
             L, DE, DE, DE, DE, DE, 1.0f, 0.0f, 0, 1, 0, 0, NH);
        gemm(xnb, 0, Wkb + (long long)l * NH * DE * DE, (long long)DE * DE,
             Kb, (long long)L * DE, bk + (long long)l * NH * DE, DE, nullptr,
             L, DE, DE, DE, DE, DE, 1.0f, 0.0f, 0, 1, 0, 0, NH);

        // packed V projection -> vselT [YCOLS][L] (transposed store)
        pack_wsel_kernel<<<(YCOLS * DE + 255) / 256, 256>>>(Wv, bv, WselT, bsel, l);
        gemm(xnb, 0, WselT, 0, vselT, 0, bsel, 0, nullptr,
             L, YCOLS, DE, DE, DE, 0, 1.0f, 0.0f, 0, 1, 1, L, 1);

        // scores = Q @ K^T / sqrt(DE) -> bf16 S
        gemm(Qb, (long long)L * DE, Kb, (long long)L * DE,
             S, (long long)L * L, nullptr, 0, nullptr,
             L, L, DE, DE, DE, L, inv_sqrt_de, 0.0f, 0, 1, 0, 0, NH);

        // row softmax (bf16 in-place)
        softmax2048_kernel<<<NH * L, 256>>>(S);

        // heads 0..10: gemv into ya[:,h]
        attn_gemv_kernel<<<dim3(L, 1, NH - 1), 256>>>(S, vselT, ya);
        // head 11: [L,64] = S_11 @ vselT[11:75]^T
        gemm(S + (long long)(NH - 1) * L * L, 0, vselT + (long long)(NH - 1) * L, 0,
             ya + (NH - 1), 0, nullptr, 0, nullptr,
             L, DV, L, L, L, YCOLS, 1.0f, 0.0f, 0, 1, 0, 0, 1);

        // Y = 2*Y + (ya @ Wo^T + bo), K = 80 (cols 75..79 of ya are zero)
        gemm(ya, 0, Wob + (long long)l * DE * YCOLS, 0, Y, 0,
             bo + l * DE, 0, Y,
             L, DE, YCOLS, YCOLS, YCOLS, DE, 1.0f, 2.0f, 2, 0, 0, 0, 1);

        // zn = LN(Y; g2, be2) -> fp32 + bf16
        ln_kernel<<<L, 256>>>(Y, znb, zn, g2 + l * DE, be2 + l * DE);

        // mlp = gelu(zn @ W1 + bm1) -> bf16
        gemm(znb, 0, W1b + (long long)l * DMLP * DE, 0, mlp, 0,
             bm1 + (long long)l * DMLP, 0, nullptr,
             L, DMLP, DE, DE, DE, DMLP, 1.0f, 0.0f, 1, 1, 0, 0, 1);

        // R = Y + zn ; Y = R + (mlp @ W2 + bm2)
        add_kernel<<<(L * DE + 255) / 256, 256>>>(Y, zn, R);
        gemm(mlp, 0, W2b + (long long)l * DE * DMLP, 0, Y, 0,
             bm2 + l * DE, 0, R,
             L, DE, DMLP, DMLP, DMLP, DE, 1.0f, 1.0f, 2, 0, 0, 0, 1);
    }

    // final LN + vocab projection (bf16 logits) + softmax -> fp32 out
    ln_kernel<<<L, 256>>>(Y, xnb, nullptr, gf, bef);
    gemm(xnb, 0, Wub, 0, lg, 0, bu, 0, nullptr,
         L, VOCAB, DE, DE, DE, VOCAB, 1.0f, 0.0f, 0, 1, 0, 0, 1);
    softmax_vocab_kernel<<<L, 256>>>(lg, out);
}